// round 9
// baseline (speedup 1.0000x reference)
#include <cuda_runtime.h>
#include <cuda_fp16.h>

#define XSB 144              // x smem row stride, bytes (72 halves)
#define WSB 144              // w smem row stride, bytes
#define CS  264              // epilogue row stride, floats

#define SM_XHI 0
#define SM_XLO 39168         // 272*144
#define SM_W   78336
#define SMEM_TOTAL (78336 + 2*64*WSB)   // 96768

__device__ __align__(16) __half g_wh[16*64*64];   // [k][f][c] fp16

__global__ void prep_w(const float* w) {
    int i = blockIdx.x*256 + threadIdx.x;         // input layout [f][c][k]
    int k = i & 15, c = (i >> 4) & 63, f = i >> 10;
    g_wh[k*4096 + f*64 + c] = __float2half_rn(w[i]);
}

__device__ __forceinline__ void ldsm4(unsigned* r, unsigned a) {
    asm volatile("ldmatrix.sync.aligned.m8n8.x4.shared.b16 {%0,%1,%2,%3}, [%4];"
        : "=r"(r[0]), "=r"(r[1]), "=r"(r[2]), "=r"(r[3]) : "r"(a));
}
__device__ __forceinline__ void mma16(float* c, const unsigned* a, const unsigned* b) {
    asm volatile("mma.sync.aligned.m16n8k16.row.col.f32.f16.f16.f32 "
        "{%0,%1,%2,%3},{%4,%5,%6,%7},{%8,%9},{%0,%1,%2,%3};"
        : "+f"(c[0]), "+f"(c[1]), "+f"(c[2]), "+f"(c[3])
        : "r"(a[0]), "r"(a[1]), "r"(a[2]), "r"(a[3]), "r"(b[0]), "r"(b[1]));
}
__device__ __forceinline__ void cpa16(unsigned s, const void* g) {
    asm volatile("cp.async.ca.shared.global [%0], [%1], 16;" :: "r"(s), "l"(g));
}

extern __shared__ unsigned char smraw[];

__device__ __forceinline__ void stage_w(unsigned sb, int k, int stage, int tid) {
    unsigned dst = sb + SM_W + stage*(64*WSB);
    #pragma unroll
    for (int r = 0; r < 2; r++) {
        int i = r*256 + tid;
        int f = i >> 3, seg = i & 7;
        cpa16(dst + f*WSB + seg*16, g_wh + k*4096 + f*64 + seg*8);
    }
    asm volatile("cp.async.commit_group;" ::: "memory");
}

__global__ void __launch_bounds__(256, 2)
conv_main(const float* __restrict__ x, const float* __restrict__ bias, float* __restrict__ out) {
    const int t0 = blockIdx.x * 256;
    const int n  = blockIdx.y;
    const int tid = threadIdx.x;
    unsigned sb;
    asm("{.reg .u64 t; cvta.to.shared.u64 t,%1; cvt.u32.u64 %0,t;}" : "=r"(sb) : "l"(smraw));

    // x window [272 t][64 c], fp16 hi/lo split
    const float* xb = x + n*64*4096;
    for (int i = tid; i < 64*272; i += 256) {
        int c = i / 272, t = i - c*272;
        int tg = t0 + t;
        float v = (tg < 4096) ? xb[c*4096 + tg] : 0.f;
        __half h = __float2half_rn(v);
        *(__half*)(smraw + SM_XHI + t*XSB + c*2) = h;
        *(__half*)(smraw + SM_XLO + t*XSB + c*2) = __float2half_rn(v - __half2float(h));
    }

    const int wid = tid >> 5, lane = tid & 31;    // 8 warps: warp = 32t x 64f
    const unsigned aoff = (lane & 15)*XSB + (lane >> 4)*16;
    const unsigned boff = ((lane & 7) + ((lane >> 4) & 1)*8)*WSB + ((lane >> 3) & 1)*16;
    float acc[2][8][4] = {};

    stage_w(sb, 0, 0, tid);
    asm volatile("cp.async.wait_group 0;" ::: "memory");
    __syncthreads();

    for (int k = 0; k < 16; k++) {
        int s = k & 1;
        if (k < 15) stage_w(sb, k + 1, s ^ 1, tid);
        const unsigned xh = sb + SM_XHI + (wid*32 + k)*XSB + aoff;
        const unsigned xl = xh + (SM_XLO - SM_XHI);
        const unsigned wb = sb + SM_W + s*(64*WSB) + boff;

        unsigned ah[2][2][4], bf[2][4][4], al[2][4];
        // preload chunk 0 (hi + B)
        ldsm4(ah[0][0], xh);
        ldsm4(ah[0][1], xh + 16*XSB);
        #pragma unroll
        for (int q = 0; q < 4; q++) ldsm4(bf[0][q], wb + q*16*WSB);

        #pragma unroll
        for (int cc = 0; cc < 4; cc++) {
            const int cur = cc & 1, nxt = cur ^ 1;
            // this chunk's lo fragments
            ldsm4(al[0], xl + cc*32);
            ldsm4(al[1], xl + 16*XSB + cc*32);
            // prefetch next chunk's hi + B under this chunk's MMAs
            if (cc < 3) {
                ldsm4(ah[nxt][0], xh + (cc+1)*32);
                ldsm4(ah[nxt][1], xh + 16*XSB + (cc+1)*32);
                #pragma unroll
                for (int q = 0; q < 4; q++) ldsm4(bf[nxt][q], wb + q*16*WSB + (cc+1)*32);
            }
            #pragma unroll
            for (int nt = 0; nt < 8; nt++) {
                const unsigned* b = &bf[cur][nt >> 1][(nt & 1)*2];
                mma16(acc[0][nt], ah[cur][0], b);
                mma16(acc[1][nt], ah[cur][1], b);
            }
            #pragma unroll
            for (int nt = 0; nt < 8; nt++) {
                const unsigned* b = &bf[cur][nt >> 1][(nt & 1)*2];
                mma16(acc[0][nt], al[0], b);
                mma16(acc[1][nt], al[1], b);
            }
        }
        if (k < 15) asm volatile("cp.async.wait_group 0;" ::: "memory");
        __syncthreads();
    }

    // epilogue: transpose through smem (reuses x region)
    float* csm = (float*)smraw;                   // [64][CS]
    const int g = lane >> 2, tq = lane & 3;
    #pragma unroll
    for (int mt = 0; mt < 2; mt++)
        #pragma unroll
        for (int nt = 0; nt < 8; nt++) {
            int f = nt*8 + 2*tq;
            int r = wid*32 + mt*16 + g;
            csm[f*CS + r]         = acc[mt][nt][0];
            csm[(f+1)*CS + r]     = acc[mt][nt][1];
            csm[f*CS + r + 8]     = acc[mt][nt][2];
            csm[(f+1)*CS + r + 8] = acc[mt][nt][3];
        }
    __syncthreads();
    float* ob = out + n*64*4081;
    for (int i = tid; i < 64*256; i += 256) {
        int f = i >> 8, t = i & 255;
        int tg = t0 + t;
        if (tg < 4081) ob[f*4081 + tg] = csm[f*CS + t] + __ldg(bias + f);
    }
}

extern "C" void kernel_launch(void* const* d_in, const int* in_sizes, int n_in,
                              void* d_out, int out_size) {
    const float* x = (const float*)d_in[0];
    const float* w = (const float*)d_in[1];
    const float* b = (const float*)d_in[2];
    float* out = (float*)d_out;
    (void)in_sizes; (void)n_in; (void)out_size;

    cudaFuncSetAttribute(conv_main, cudaFuncAttributeMaxDynamicSharedMemorySize, SMEM_TOTAL);
    prep_w<<<256, 256>>>(w);
    conv_main<<<dim3(16, 64), 256, SMEM_TOTAL>>>(x, b, out);
}

// round 10
// speedup vs baseline: 1.4378x; 1.4378x over previous
#include <cuda_runtime.h>
#include <cuda_fp16.h>

#define XSB 144              // x smem row stride, bytes (72 halves)
#define WSB 144              // w smem row stride, bytes
#define CS  264              // epilogue row stride, floats

#define SM_XHI 0
#define SM_W   39168         // 272*144
#define SMEM_TOTAL 67584     // max(compute 57600, epilogue 64*264*4)

__device__ __align__(16) __half g_wh[16*64*64];   // [k][f][c] fp16

__global__ void prep_w(const float* w) {
    int i = blockIdx.x*256 + threadIdx.x;         // input layout [f][c][k]
    int k = i & 15, c = (i >> 4) & 63, f = i >> 10;
    g_wh[k*4096 + f*64 + c] = __float2half_rn(w[i]);
}

__device__ __forceinline__ void ldsm4(unsigned* r, unsigned a) {
    asm volatile("ldmatrix.sync.aligned.m8n8.x4.shared.b16 {%0,%1,%2,%3}, [%4];"
        : "=r"(r[0]), "=r"(r[1]), "=r"(r[2]), "=r"(r[3]) : "r"(a));
}
__device__ __forceinline__ void mma16(float* c, const unsigned* a, const unsigned* b) {
    asm volatile("mma.sync.aligned.m16n8k16.row.col.f32.f16.f16.f32 "
        "{%0,%1,%2,%3},{%4,%5,%6,%7},{%8,%9},{%0,%1,%2,%3};"
        : "+f"(c[0]), "+f"(c[1]), "+f"(c[2]), "+f"(c[3])
        : "r"(a[0]), "r"(a[1]), "r"(a[2]), "r"(a[3]), "r"(b[0]), "r"(b[1]));
}
__device__ __forceinline__ void cpa16(unsigned s, const void* g) {
    asm volatile("cp.async.ca.shared.global [%0], [%1], 16;" :: "r"(s), "l"(g));
}

extern __shared__ unsigned char smraw[];

__device__ __forceinline__ void stage_w(unsigned sb, int k, int stage, int tid) {
    unsigned dst = sb + SM_W + stage*(64*WSB);
    #pragma unroll
    for (int r = 0; r < 2; r++) {
        int i = r*256 + tid;
        int f = i >> 3, seg = i & 7;
        cpa16(dst + f*WSB + seg*16, g_wh + k*4096 + f*64 + seg*8);
    }
    asm volatile("cp.async.commit_group;" ::: "memory");
}

__global__ void __launch_bounds__(256, 2)
conv_main(const float* __restrict__ x, const float* __restrict__ bias, float* __restrict__ out) {
    const int t0 = blockIdx.x * 256;
    const int n  = blockIdx.y;
    const int tid = threadIdx.x;
    unsigned sb;
    asm("{.reg .u64 t; cvta.to.shared.u64 t,%1; cvt.u32.u64 %0,t;}" : "=r"(sb) : "l"(smraw));

    // x window [272 t][64 c], fp16 (single image)
    const float* xb = x + n*64*4096;
    for (int i = tid; i < 64*272; i += 256) {
        int c = i / 272, t = i - c*272;
        int tg = t0 + t;
        float v = (tg < 4096) ? xb[c*4096 + tg] : 0.f;
        *(__half*)(smraw + SM_XHI + t*XSB + c*2) = __float2half_rn(v);
    }

    const int wid = tid >> 5, lane = tid & 31;    // 8 warps: warp = 32t x 64f
    const unsigned aoff = (lane & 15)*XSB + (lane >> 4)*16;
    const unsigned boff = ((lane & 7) + ((lane >> 4) & 1)*8)*WSB + ((lane >> 3) & 1)*16;
    float acc[2][8][4] = {};

    stage_w(sb, 0, 0, tid);
    asm volatile("cp.async.wait_group 0;" ::: "memory");
    __syncthreads();

    for (int k = 0; k < 16; k++) {
        int s = k & 1;
        if (k < 15) stage_w(sb, k + 1, s ^ 1, tid);
        unsigned xh = sb + SM_XHI + (wid*32 + k)*XSB + aoff;
        unsigned wb = sb + SM_W + s*(64*WSB) + boff;
        #pragma unroll
        for (int cc = 0; cc < 64; cc += 16) {
            unsigned ah[2][4], bf[4][4];
            ldsm4(ah[0], xh + cc*2);
            ldsm4(ah[1], xh + 16*XSB + cc*2);
            #pragma unroll
            for (int q = 0; q < 4; q++) ldsm4(bf[q], wb + q*16*WSB + cc*2);
            #pragma unroll
            for (int nt = 0; nt < 8; nt++) {
                const unsigned* b = &bf[nt >> 1][(nt & 1)*2];
                mma16(acc[0][nt], ah[0], b);
                mma16(acc[1][nt], ah[1], b);
            }
        }
        if (k < 15) asm volatile("cp.async.wait_group 0;" ::: "memory");
        __syncthreads();
    }

    // epilogue: transpose through smem
    float* csm = (float*)smraw;                   // [64][CS]
    const int g = lane >> 2, tq = lane & 3;
    #pragma unroll
    for (int mt = 0; mt < 2; mt++)
        #pragma unroll
        for (int nt = 0; nt < 8; nt++) {
            int f = nt*8 + 2*tq;
            int r = wid*32 + mt*16 + g;
            csm[f*CS + r]         = acc[mt][nt][0];
            csm[(f+1)*CS + r]     = acc[mt][nt][1];
            csm[f*CS + r + 8]     = acc[mt][nt][2];
            csm[(f+1)*CS + r + 8] = acc[mt][nt][3];
        }
    __syncthreads();
    float* ob = out + n*64*4081;
    for (int i = tid; i < 64*256; i += 256) {
        int f = i >> 8, t = i & 255;
        int tg = t0 + t;
        if (tg < 4081) ob[f*4081 + tg] = csm[f*CS + t] + __ldg(bias + f);
    }
}

extern "C" void kernel_launch(void* const* d_in, const int* in_sizes, int n_in,
                              void* d_out, int out_size) {
    const float* x = (const float*)d_in[0];
    const float* w = (const float*)d_in[1];
    const float* b = (const float*)d_in[2];
    float* out = (float*)d_out;
    (void)in_sizes; (void)n_in; (void)out_size;

    cudaFuncSetAttribute(conv_main, cudaFuncAttributeMaxDynamicSharedMemorySize, SMEM_TOTAL);
    prep_w<<<256, 256>>>(w);
    conv_main<<<dim3(16, 64), 256, SMEM_TOTAL>>>(x, b, out);
}

// round 11
// speedup vs baseline: 1.4700x; 1.0224x over previous
#include <cuda_runtime.h>
#include <cuda_fp16.h>

#define XSB 144              // x smem row stride, bytes (72 halves)
#define WSB 144              // w smem row stride, bytes
#define CS  132              // epilogue row stride, floats

#define SM_XHI 0
#define SM_W   20736         // 144*144
#define SMEM_TOTAL 39168     // x(20736) + w stages(18432); epilogue 33792 reuses

__device__ __align__(16) __half g_wh[16*64*64];   // [k][f][c] fp16

__global__ void prep_w(const float* w) {
    int i = blockIdx.x*256 + threadIdx.x;         // input layout [f][c][k]
    int k = i & 15, c = (i >> 4) & 63, f = i >> 10;
    g_wh[k*4096 + f*64 + c] = __float2half_rn(w[i]);
}

__device__ __forceinline__ void ldsm4(unsigned* r, unsigned a) {
    asm volatile("ldmatrix.sync.aligned.m8n8.x4.shared.b16 {%0,%1,%2,%3}, [%4];"
        : "=r"(r[0]), "=r"(r[1]), "=r"(r[2]), "=r"(r[3]) : "r"(a));
}
__device__ __forceinline__ void mma16(float* c, const unsigned* a, const unsigned* b) {
    asm volatile("mma.sync.aligned.m16n8k16.row.col.f32.f16.f16.f32 "
        "{%0,%1,%2,%3},{%4,%5,%6,%7},{%8,%9},{%0,%1,%2,%3};"
        : "+f"(c[0]), "+f"(c[1]), "+f"(c[2]), "+f"(c[3])
        : "r"(a[0]), "r"(a[1]), "r"(a[2]), "r"(a[3]), "r"(b[0]), "r"(b[1]));
}
__device__ __forceinline__ void cpa16(unsigned s, const void* g) {
    asm volatile("cp.async.ca.shared.global [%0], [%1], 16;" :: "r"(s), "l"(g));
}

extern __shared__ unsigned char smraw[];

__device__ __forceinline__ void stage_w(unsigned sb, int k, int stage, int tid) {
    unsigned dst = sb + SM_W + stage*(64*WSB);
    #pragma unroll
    for (int r = 0; r < 4; r++) {
        int i = r*128 + tid;                      // 512 chunks of 16B
        int f = i >> 3, seg = i & 7;
        cpa16(dst + f*WSB + seg*16, g_wh + k*4096 + f*64 + seg*8);
    }
    asm volatile("cp.async.commit_group;" ::: "memory");
}

__global__ void __launch_bounds__(128, 4)
conv_main(const float* __restrict__ x, const float* __restrict__ bias, float* __restrict__ out) {
    const int t0 = blockIdx.x * 128;
    const int n  = blockIdx.y;
    const int tid = threadIdx.x;
    unsigned sb;
    asm("{.reg .u64 t; cvta.to.shared.u64 t,%1; cvt.u32.u64 %0,t;}" : "=r"(sb) : "l"(smraw));

    // x window [144 t][64 c], fp16
    const float* xb = x + n*64*4096;
    for (int i = tid; i < 64*144; i += 128) {
        int c = i / 144, t = i - c*144;
        int tg = t0 + t;
        float v = (tg < 4096) ? xb[c*4096 + tg] : 0.f;
        *(__half*)(smraw + SM_XHI + t*XSB + c*2) = __float2half_rn(v);
    }

    const int wid = tid >> 5, lane = tid & 31;    // 4 warps: warp = 32t x 64f
    const unsigned aoff = (lane & 15)*XSB + (lane >> 4)*16;
    const unsigned boff = ((lane & 7) + ((lane >> 4) & 1)*8)*WSB + ((lane >> 3) & 1)*16;
    float acc[2][8][4] = {};

    stage_w(sb, 0, 0, tid);
    asm volatile("cp.async.wait_group 0;" ::: "memory");
    __syncthreads();

    for (int k = 0; k < 16; k++) {
        int s = k & 1;
        if (k < 15) stage_w(sb, k + 1, s ^ 1, tid);
        unsigned xh = sb + SM_XHI + (wid*32 + k)*XSB + aoff;
        unsigned wb = sb + SM_W + s*(64*WSB) + boff;
        #pragma unroll
        for (int cc = 0; cc < 64; cc += 16) {
            unsigned ah[2][4], bf[4][4];
            ldsm4(ah[0], xh + cc*2);
            ldsm4(ah[1], xh + 16*XSB + cc*2);
            #pragma unroll
            for (int q = 0; q < 4; q++) ldsm4(bf[q], wb + q*16*WSB + cc*2);
            #pragma unroll
            for (int nt = 0; nt < 8; nt++) {
                const unsigned* b = &bf[nt >> 1][(nt & 1)*2];
                mma16(acc[0][nt], ah[0], b);
                mma16(acc[1][nt], ah[1], b);
            }
        }
        if (k < 15) asm volatile("cp.async.wait_group 0;" ::: "memory");
        __syncthreads();
    }

    // epilogue: transpose through smem (reuses x region)
    float* csm = (float*)smraw;                   // [64][CS]
    const int g = lane >> 2, tq = lane & 3;
    #pragma unroll
    for (int mt = 0; mt < 2; mt++)
        #pragma unroll
        for (int nt = 0; nt < 8; nt++) {
            int f = nt*8 + 2*tq;
            int r = wid*32 + mt*16 + g;
            csm[f*CS + r]         = acc[mt][nt][0];
            csm[(f+1)*CS + r]     = acc[mt][nt][1];
            csm[f*CS + r + 8]     = acc[mt][nt][2];
            csm[(f+1)*CS + r + 8] = acc[mt][nt][3];
        }
    __syncthreads();
    float* ob = out + n*64*4081;
    for (int i = tid; i < 64*128; i += 128) {
        int f = i >> 7, t = i & 127;
        int tg = t0 + t;
        if (tg < 4081) ob[f*4081 + tg] = csm[f*CS + t] + __ldg(bias + f);
    }
}

extern "C" void kernel_launch(void* const* d_in, const int* in_sizes, int n_in,
                              void* d_out, int out_size) {
    const float* x = (const float*)d_in[0];
    const float* w = (const float*)d_in[1];
    const float* b = (const float*)d_in[2];
    float* out = (float*)d_out;
    (void)in_sizes; (void)n_in; (void)out_size;

    cudaFuncSetAttribute(conv_main, cudaFuncAttributeMaxDynamicSharedMemorySize, SMEM_TOTAL);
    prep_w<<<256, 256>>>(w);
    conv_main<<<dim3(32, 64), 128, SMEM_TOTAL>>>(x, b, out);
}